// round 1
// baseline (speedup 1.0000x reference)
#include <cuda_runtime.h>
#include <math.h>

#define NV    8192
#define DEG   16
#define EMBD  512
#define NPCC  256
#define NL    257      // NPC + 1
#define H2D   400
#define NCTA  8
#define TPB   1024
#define GSTRIDE (NCTA*TPB)

// Persistent state (static device globals: allowed scratch)
__device__ float g_z[(size_t)NV * EMBD];   // z[u] = emb[u] @ W[:512]   (16 MB)
__device__ int   g_colors[NV];
__device__ float g_h1[EMBD];
__device__ float g_h2[H2D];
__device__ float g_logits[NL];
__device__ float g_red[NCTA * 4];
__device__ int   g_nused;
__device__ float g_lpp;

__device__ __forceinline__ float wsum(float v) {
#pragma unroll
    for (int o = 16; o; o >>= 1) v += __shfl_xor_sync(0xffffffffu, v, o);
    return v;
}

#define CLUSTER_SYNC() do { \
    asm volatile("barrier.cluster.arrive.aligned;" ::: "memory"); \
    asm volatile("barrier.cluster.wait.aligned;"   ::: "memory"); } while (0)

__global__ void __launch_bounds__(TPB, 1) __cluster_dims__(NCTA, 1, 1)
gc_kernel(const int* __restrict__ adj, const float* __restrict__ W,
          const float* __restrict__ a, const float* __restrict__ fc1w,
          const float* __restrict__ fc1b, const float* __restrict__ fc2w,
          const float* __restrict__ fc2b, const float* __restrict__ fc3w,
          const float* __restrict__ fc3b, const int* __restrict__ baseline,
          float* __restrict__ out, int out_size)
{
    __shared__ float sh_h[17][EMBD];    // gathered h rows (GAT)
    __shared__ float sh_ne[EMBD];       // new_e; reused to stage h1 / h2
    __shared__ float sh_a1[EMBD], sh_a2[EMBD];
    __shared__ float sh_e[20];
    __shared__ float sh_attn[20];
    __shared__ int   sh_nbrc[20];
    __shared__ float sh_red[40];
    __shared__ int   sh_redi[40];

    const int rank = blockIdx.x;
    const int tid  = threadIdx.x;
    const int warp = tid >> 5, lane = tid & 31;
    const int gtid = rank * TPB + tid;

    // ---------- init (must run every launch: graph replays reuse state) ----------
    {
        float4 z4 = make_float4(0.f, 0.f, 0.f, 0.f);
        float4* zp = (float4*)g_z;
        const size_t nz4 = (size_t)NV * EMBD / 4;
        for (size_t i = gtid; i < nz4; i += GSTRIDE) zp[i] = z4;
    }
    for (int i = gtid; i < NV; i += GSTRIDE) g_colors[i] = (i == 0) ? 0 : -1;
    for (int i = tid; i < EMBD; i += TPB) { sh_a1[i] = a[i]; sh_a2[i] = a[EMBD + i]; }
    if (rank == 0 && tid == 0) { g_nused = 1; g_lpp = 0.f; }

    // ---------- weight Frobenius norms (deterministic fixed-order reduce) ----------
    {
        float s[4] = {0.f, 0.f, 0.f, 0.f};
        for (int i = gtid; i < 768 * 512; i += GSTRIDE) { float x = W[i];    s[0] += x * x; }
        for (int i = gtid; i < 512 * 512; i += GSTRIDE) { float x = fc1w[i]; s[1] += x * x; }
        for (int i = gtid; i < 400 * 512; i += GSTRIDE) { float x = fc2w[i]; s[2] += x * x; }
        for (int i = gtid; i < 257 * 400; i += GSTRIDE) { float x = fc3w[i]; s[3] += x * x; }
#pragma unroll
        for (int m = 0; m < 4; m++) {
            float w = wsum(s[m]);
            __syncthreads();
            if (lane == 0) sh_red[warp] = w;
            __syncthreads();
            if (warp == 0) {
                float v2 = sh_red[lane];
                v2 = wsum(v2);
                if (lane == 0) g_red[rank * 4 + m] = v2;
            }
        }
    }
    __syncthreads();
    CLUSTER_SYNC();

    float regv = 0.f;
    if (rank == 0 && tid == 0) {
        for (int m = 0; m < 4; m++) {
            float ssq = 0.f;
            for (int r2 = 0; r2 < NCTA; r2++) ssq += g_red[r2 * 4 + m];
            regv += sqrtf(ssq);
        }
    }

    // =======================  main sequential scan  =======================
    for (int v = 1; v < NV; ++v) {
        // ---- Stage A: gather h rows, e-dots, softmax, new_e (replicated per CTA) ----
        if (warp < 17) {
            int u = (warp == 0) ? v : adj[v * DEG + warp - 1];
            int c = g_colors[u];
            if (lane == 0) sh_nbrc[warp] = c;
            const float* zrow = g_z + (size_t)u * EMBD;
            const float* wrow = ((unsigned)c < NPCC) ? (W + (size_t)(EMBD + c) * EMBD) : (const float*)0;
            float d2 = 0.f, d1 = 0.f;
#pragma unroll
            for (int k = 0; k < 16; k++) {
                int j = lane + 32 * k;
                float hv = zrow[j];
                if (wrow) hv += wrow[j];
                sh_h[warp][j] = hv;
                d2 += hv * sh_a2[j];
                if (warp == 0) d1 += hv * sh_a1[j];
            }
            d2 = wsum(d2);
            if (warp == 0) d1 = wsum(d1);
            if (lane == 0) { sh_e[warp] = d2; if (warp == 0) sh_e[17] = d1; }
        }
        __syncthreads();
        if (warp == 0) {
            float d0 = sh_e[17];
            float ev = -INFINITY;
            if (lane < 17) { float t = d0 + sh_e[lane]; ev = (t > 0.f) ? t : 0.2f * t; }
            float m = ev;
#pragma unroll
            for (int o = 16; o; o >>= 1) m = fmaxf(m, __shfl_xor_sync(0xffffffffu, m, o));
            float p = (lane < 17) ? expf(ev - m) : 0.f;
            float ssum = wsum(p);
            if (lane < 17) sh_attn[lane] = p / ssum;
        }
        __syncthreads();
        if (tid < EMBD) {
            float acc = 0.f;
#pragma unroll
            for (int i = 0; i < 17; i++) acc += sh_attn[i] * sh_h[i][tid];
            sh_ne[tid] = (acc > 0.f) ? acc : expm1f(acc);   // elu
        }
        __syncthreads();

        // ---- Stage B: z[v] (W_emb columns) + h1 (fc1 rows), split across cluster ----
        if (warp >= 30) {
            // z columns: lane-per-column, coalesced over j
            int j = rank * 64 + (warp - 30) * 32 + lane;
            float a0 = 0.f, b0 = 0.f, c0 = 0.f, d0 = 0.f;
            for (int k = 0; k < EMBD; k += 4) {
                a0 += sh_ne[k    ] * W[(size_t)(k    ) * EMBD + j];
                b0 += sh_ne[k + 1] * W[(size_t)(k + 1) * EMBD + j];
                c0 += sh_ne[k + 2] * W[(size_t)(k + 2) * EMBD + j];
                d0 += sh_ne[k + 3] * W[(size_t)(k + 3) * EMBD + j];
            }
            g_z[(size_t)v * EMBD + j] = (a0 + b0) + (c0 + d0);
        } else {
            // h1 rows: warp-per-row, lanes over k (coalesced), shfl reduce
            for (int r0 = warp; r0 < 64; r0 += 30) {
                int r = rank * 64 + r0;
                const float* wr = fc1w + (size_t)r * EMBD;
                float acc = 0.f;
#pragma unroll
                for (int k = lane; k < EMBD; k += 32) acc += sh_ne[k] * wr[k];
                acc = wsum(acc);
                if (lane == 0) { float t = acc + fc1b[r]; g_h1[r] = (t > 0.f) ? t : 0.01f * t; }
            }
        }
        CLUSTER_SYNC();

        // ---- Stage C: h2 = lrelu(fc2 @ h1 + b) ----
        if (tid < EMBD) sh_ne[tid] = g_h1[tid];
        __syncthreads();
        for (int r0 = warp; r0 < 50; r0 += 32) {
            int r = rank * 50 + r0;
            const float* wr = fc2w + (size_t)r * EMBD;
            float acc = 0.f;
#pragma unroll
            for (int k = lane; k < EMBD; k += 32) acc += sh_ne[k] * wr[k];
            acc = wsum(acc);
            if (lane == 0) { float t = acc + fc2b[r]; g_h2[r] = (t > 0.f) ? t : 0.01f * t; }
        }
        CLUSTER_SYNC();

        // ---- Stage D: logits = fc3 @ h2 + b ----
        if (tid < H2D) sh_ne[tid] = g_h2[tid];
        __syncthreads();
        for (int r0 = warp; r0 < 33; r0 += 32) {
            int r = rank * 33 + r0;
            if (r < NL) {
                const float* wr = fc3w + (size_t)r * H2D;
                float acc = 0.f;
                for (int k = lane; k < H2D; k += 32) acc += sh_ne[k] * wr[k];
                acc = wsum(acc);
                if (lane == 0) g_logits[r] = acc + fc3b[r];
            }
        }
        CLUSTER_SYNC();

        // ---- Stage E: mask + argmax + state update (redundant; commit on rank0/t0) ----
        int nused = g_nused;
        float mlv; int mii;
        if (tid < NL) {
            float L = g_logits[tid];
            bool irrel = (tid >= nused) && (tid < NPCC);
            bool am = false;
#pragma unroll
            for (int i = 1; i < 17; i++) am |= (sh_nbrc[i] == tid);
            mlv = (irrel || am) ? -INFINITY : L;
            mii = tid;
        } else { mlv = -INFINITY; mii = 0x7fffffff; }
        {
            float rv = mlv; int ri = mii;
#pragma unroll
            for (int o = 16; o; o >>= 1) {
                float ov = __shfl_xor_sync(0xffffffffu, rv, o);
                int   oi = __shfl_xor_sync(0xffffffffu, ri, o);
                if (ov > rv || (ov == rv && oi < ri)) { rv = ov; ri = oi; }
            }
            if (lane == 0) { sh_red[warp] = rv; sh_redi[warp] = ri; }
        }
        __syncthreads();
        if (warp == 0) {
            float v2 = sh_red[lane]; int i2 = sh_redi[lane];
#pragma unroll
            for (int o = 16; o; o >>= 1) {
                float ov = __shfl_xor_sync(0xffffffffu, v2, o);
                int   oi = __shfl_xor_sync(0xffffffffu, i2, o);
                if (ov > v2 || (ov == v2 && oi < i2)) { v2 = ov; i2 = oi; }
            }
            if (lane == 0) { sh_red[32] = v2; sh_redi[32] = i2; }
        }
        __syncthreads();
        float mx = sh_red[32];
        int   mix = sh_redi[32];
        float pe = (tid < NL) ? expf(mlv - mx) : 0.f;   // winner contributes exp(0)=1
        pe = wsum(pe);
        if (lane == 0) sh_red[warp] = pe;               // [0..31], does not clobber [32]
        __syncthreads();
        if (rank == 0 && tid == 0) {
            float s = 0.f;
            for (int w2 = 0; w2 < 32; w2++) s += sh_red[w2];
            int isnew  = (mix == NPCC);
            int chosen = isnew ? nused : mix;
            g_colors[v] = chosen;
            if (isnew) g_nused = nused + 1;
            // max(probs) = exp(mx - mx)/s = 1/s ;  lpp += log(maxp+1e-8) - log(1e-8)
            g_lpp += logf(1.f / s + 1e-8f) + 18.420680743952367f;
        }
        CLUSTER_SYNC();
    }

    // ---------- output: [colors as float..., loss] ----------
    for (int i = gtid; i < NV && i < out_size; i += GSTRIDE) out[i] = (float)g_colors[i];
    if (rank == 0 && tid == 0 && out_size > NV) {
        float loss = ((float)g_nused - (float)baseline[0]) * g_lpp / (float)NV + 0.05f * regv;
        out[NV] = loss;
    }
}

extern "C" void kernel_launch(void* const* d_in, const int* in_sizes, int n_in,
                              void* d_out, int out_size) {
    (void)in_sizes; (void)n_in;
    gc_kernel<<<NCTA, TPB>>>(
        (const int*)d_in[0],    // adj      (8192,16) int32
        (const float*)d_in[1],  // W        (768,512)
        (const float*)d_in[2],  // a        (1024,)
        (const float*)d_in[3],  // fc1_w    (512,512)
        (const float*)d_in[4],  // fc1_b    (512,)
        (const float*)d_in[5],  // fc2_w    (400,512)
        (const float*)d_in[6],  // fc2_b    (400,)
        (const float*)d_in[7],  // fc3_w    (257,400)
        (const float*)d_in[8],  // fc3_b    (257,)
        (const int*)d_in[9],    // baseline (scalar; first 4 bytes == 50 for i32/i64)
        (float*)d_out, out_size);
}

// round 2
// speedup vs baseline: 1.6897x; 1.6897x over previous
#include <cuda_runtime.h>
#include <math.h>

#define NV    8192
#define DEG   16
#define EMBD  512
#define NPCC  256
#define NL    257
#define H2D   400
#define NCTA  8
#define TPB   512
#define NW    16
#define GSTRIDE (NCTA*TPB)

// Persistent device scratch
__device__ __align__(16) float g_z[(size_t)NV * EMBD];    // z[u] = emb[u] @ W[:512]
__device__ __align__(16) float g_wt[EMBD * EMBD];         // W[:512] transposed
__device__ int    g_colors[NV];
__device__ __align__(16) float g_h1[EMBD];
__device__ __align__(16) float g_h2[H2D + 16];
__device__ float4 g_tri[NCTA];                            // (lmax, lsum, argmax_as_float, 0)
__device__ float  g_red[NCTA * 4];

__device__ __forceinline__ float wsum(float v) {
#pragma unroll
    for (int o = 16; o; o >>= 1) v += __shfl_xor_sync(0xffffffffu, v, o);
    return v;
}
__device__ __forceinline__ float dot4(float4 a, float4 b) {
    return a.x*b.x + a.y*b.y + a.z*b.z + a.w*b.w;
}

#define CLUSTER_SYNC() do { \
    asm volatile("barrier.cluster.arrive.aligned;" ::: "memory"); \
    asm volatile("barrier.cluster.wait.aligned;"   ::: "memory"); } while (0)

__global__ void __launch_bounds__(TPB, 1) __cluster_dims__(NCTA, 1, 1)
gc_kernel(const int* __restrict__ adj, const float* __restrict__ W,
          const float* __restrict__ a, const float* __restrict__ fc1w,
          const float* __restrict__ fc1b, const float* __restrict__ fc2w,
          const float* __restrict__ fc2b, const float* __restrict__ fc3w,
          const float* __restrict__ fc3b, const int* __restrict__ baseline,
          float* __restrict__ out, int out_size)
{
    __shared__ __align__(16) float sh_h[17][EMBD];   // gathered h rows
    __shared__ __align__(16) float sh_ne[EMBD];      // new_e; reused for h1/h2 staging
    __shared__ __align__(16) float sh_a1[EMBD];
    __shared__ __align__(16) float sh_a2[EMBD];
    __shared__ float sh_e[20];
    __shared__ float sh_d1;
    __shared__ float sh_attn[20];
    __shared__ int   sh_nbrc[20];
    __shared__ float sh_red[NW];
    __shared__ float sh_loc[64];                      // masked local logits (padded -inf)
    __shared__ int   sh_nused;

    const int rank = blockIdx.x;
    const int tid  = threadIdx.x;
    const int warp = tid >> 5, lane = tid & 31;
    const int gtid = rank * TPB + tid;

    float lpp  = 0.f;   // meaningful on warp0/lane0 of each CTA
    float regv = 0.f;   // meaningful on rank0 tid0

    // ---------------- init (graph replays must fully reinit) ----------------
    {
        float4 z4 = make_float4(0.f, 0.f, 0.f, 0.f);
        float4* zp = (float4*)g_z;
        const size_t nz4 = (size_t)NV * EMBD / 4;
        for (size_t i = gtid; i < nz4; i += GSTRIDE) zp[i] = z4;
    }
    for (int i = gtid; i < NV; i += GSTRIDE) g_colors[i] = (i == 0) ? 0 : -1;
    // transpose W[:512] -> g_wt
    for (int i = gtid; i < EMBD * EMBD; i += GSTRIDE) {
        int k = i >> 9, j = i & 511;
        g_wt[(size_t)j * EMBD + k] = W[i];
    }
    for (int i = tid; i < EMBD; i += TPB) { sh_a1[i] = a[i]; sh_a2[i] = a[EMBD + i]; }
    if (tid < 64) sh_loc[tid] = -INFINITY;   // slots never written stay -inf
    if (tid == 0) sh_nused = 1;

    // Frobenius norms (fixed-order, cluster-split)
    {
        float s[4] = {0.f, 0.f, 0.f, 0.f};
        for (int i = gtid; i < 768 * 512; i += GSTRIDE) { float x = W[i];    s[0] += x * x; }
        for (int i = gtid; i < 512 * 512; i += GSTRIDE) { float x = fc1w[i]; s[1] += x * x; }
        for (int i = gtid; i < 400 * 512; i += GSTRIDE) { float x = fc2w[i]; s[2] += x * x; }
        for (int i = gtid; i < 257 * 400; i += GSTRIDE) { float x = fc3w[i]; s[3] += x * x; }
#pragma unroll
        for (int m = 0; m < 4; m++) {
            float w = wsum(s[m]);
            __syncthreads();
            if (lane == 0) sh_red[warp] = w;
            __syncthreads();
            if (warp == 0) {
                float v2 = (lane < NW) ? sh_red[lane] : 0.f;
                v2 = wsum(v2);
                if (lane == 0) g_red[rank * 4 + m] = v2;
            }
        }
    }
    __syncthreads();
    CLUSTER_SYNC();

    if (rank == 0 && tid == 0) {
        for (int m = 0; m < 4; m++) {
            float ssq = 0.f;
            for (int c = 0; c < NCTA; c++) ssq += __ldcg(&g_red[c * 4 + m]);
            regv += sqrtf(ssq);
        }
    }

    const float4* ne4 = (const float4*)sh_ne;

    // ======================= sequential scan over vertices =======================
    for (int v = 1; v < NV; ++v) {
        // ---- Stage A: gather h rows + e-dots (replicated per CTA) ----
        for (int t = warp; t < 17; t += NW) {
            int u, c;
            if (t == 0) { u = v; c = -1; }
            else { u = adj[v * DEG + t - 1]; c = __ldcg(&g_colors[u]); }
            if (lane == 0) sh_nbrc[t] = c;
            const float4* z4 = (const float4*)(g_z + (size_t)u * EMBD);
            const float4* w4 = ((unsigned)c < NPCC)
                             ? (const float4*)(W + (size_t)(EMBD + c) * EMBD) : (const float4*)0;
            float d2 = 0.f, d1 = 0.f;
#pragma unroll
            for (int i = 0; i < 4; i++) {
                int idx = lane + 32 * i;
                float4 hv = __ldcg(&z4[idx]);
                if (w4) { float4 wv = w4[idx]; hv.x += wv.x; hv.y += wv.y; hv.z += wv.z; hv.w += wv.w; }
                ((float4*)sh_h[t])[idx] = hv;
                d2 += dot4(hv, ((const float4*)sh_a2)[idx]);
                if (t == 0) d1 += dot4(hv, ((const float4*)sh_a1)[idx]);
            }
            d2 = wsum(d2);
            if (t == 0) { d1 = wsum(d1); if (lane == 0) sh_d1 = d1; }
            if (lane == 0) sh_e[t] = d2;
        }
        __syncthreads();

        // ---- attention softmax (warp 0) ----
        if (warp == 0) {
            float d0 = sh_d1;
            float ev = -INFINITY;
            if (lane < 17) { float tt = d0 + sh_e[lane]; ev = (tt > 0.f) ? tt : 0.2f * tt; }
            float m = ev;
#pragma unroll
            for (int o = 16; o; o >>= 1) m = fmaxf(m, __shfl_xor_sync(0xffffffffu, m, o));
            float p = (lane < 17) ? expf(ev - m) : 0.f;
            float ssum = wsum(p);
            if (lane < 17) sh_attn[lane] = p / ssum;
        }
        __syncthreads();

        // ---- new_e = elu(attn @ h) ----
        {
            float acc = 0.f;
#pragma unroll
            for (int i = 0; i < 17; i++) acc += sh_attn[i] * sh_h[i][tid];
            sh_ne[tid] = (acc > 0.f) ? acc : expm1f(acc);
        }
        __syncthreads();

        // ---- Stage B: 128 row-dots per CTA: 64 fc1 rows + 64 z (Wt) rows ----
#pragma unroll
        for (int tt = 0; tt < 8; tt++) {
            int t = warp + NW * tt;
            const float4* row4 = (t < 64)
                ? (const float4*)(fc1w + (size_t)(rank * 64 + t) * EMBD)
                : (const float4*)(g_wt + (size_t)(rank * 64 + (t - 64)) * EMBD);
            float acc = 0.f;
#pragma unroll
            for (int i = 0; i < 4; i++) {
                int idx = lane + 32 * i;
                acc += dot4(row4[idx], ne4[idx]);
            }
            acc = wsum(acc);
            if (lane == 0) {
                if (t < 64) {
                    int r = rank * 64 + t;
                    float h = acc + fc1b[r];
                    g_h1[r] = (h > 0.f) ? h : 0.01f * h;
                } else {
                    g_z[(size_t)v * EMBD + rank * 64 + (t - 64)] = acc;
                }
            }
        }
        CLUSTER_SYNC();   // sync1: h1 complete

        // ---- Stage C: h2 = lrelu(fc2 @ h1 + b2), 50 rows per CTA ----
        if (tid < 128) ((float4*)sh_ne)[tid] = __ldcg((const float4*)g_h1 + tid);
        __syncthreads();
#pragma unroll
        for (int tt = 0; tt < 4; tt++) {
            int t = warp + NW * tt;
            if (t < 50) {
                int r = rank * 50 + t;
                const float4* row4 = (const float4*)(fc2w + (size_t)r * EMBD);
                float acc = 0.f;
#pragma unroll
                for (int i = 0; i < 4; i++) {
                    int idx = lane + 32 * i;
                    acc += dot4(row4[idx], ne4[idx]);
                }
                acc = wsum(acc);
                if (lane == 0) {
                    float h = acc + fc2b[r];
                    g_h2[r] = (h > 0.f) ? h : 0.01f * h;
                }
            }
        }
        CLUSTER_SYNC();   // sync2: h2 complete

        // ---- Stage D: local logits (33 rows), mask, local max/sum/argmax ----
        if (tid < 100) ((float4*)sh_ne)[tid] = __ldcg((const float4*)g_h2 + tid);
        __syncthreads();
        {
            int nused = sh_nused;
#pragma unroll
            for (int tt = 0; tt < 3; tt++) {
                int t = warp + NW * tt;
                int r = rank * 33 + t;
                if (t < 33 && r < NL) {
                    const float4* row4 = (const float4*)(fc3w + (size_t)r * H2D);
                    float acc = 0.f;
#pragma unroll
                    for (int i = 0; i < 4; i++) {
                        int idx = lane + 32 * i;
                        if (idx < 100) acc += dot4(row4[idx], ne4[idx]);
                    }
                    acc = wsum(acc);
                    if (lane == 0) {
                        float L = acc + fc3b[r];
                        bool irrel = (r >= nused) && (r < NPCC);
                        bool am = false;
#pragma unroll
                        for (int i = 1; i < 17; i++) am |= (sh_nbrc[i] == r);
                        sh_loc[t] = (irrel || am) ? -INFINITY : L;
                    }
                }
            }
        }
        __syncthreads();
        if (warp == 0) {   // local argmax + sum-exp over 33 slots (padded -inf)
            float v1 = sh_loc[lane];       int i1 = lane;
            float v2 = sh_loc[lane + 32];  int i2 = lane + 32;
            if (v2 > v1) { v1 = v2; i1 = i2; }
            float rv = v1; int ri = i1;
#pragma unroll
            for (int o = 16; o; o >>= 1) {
                float ov = __shfl_xor_sync(0xffffffffu, rv, o);
                int   oi = __shfl_xor_sync(0xffffffffu, ri, o);
                if (ov > rv || (ov == rv && oi < ri)) { rv = ov; ri = oi; }
            }
            float lmax = rv;
            float t0 = (sh_loc[lane]      == -INFINITY) ? 0.f : expf(sh_loc[lane]      - lmax);
            float t1 = (sh_loc[lane + 32] == -INFINITY) ? 0.f : expf(sh_loc[lane + 32] - lmax);
            float lsum = wsum(t0 + t1);
            if (lmax == -INFINITY) lsum = 0.f;
            if (lane == 0)
                g_tri[rank] = make_float4(lmax, lsum, __int_as_float(rank * 33 + ri), 0.f);
        }
        CLUSTER_SYNC();   // sync3: triples complete

        // ---- combine (replicated in every CTA, deterministic) ----
        if (warp == 0) {
            float cv = -INFINITY, cs = 0.f; int ci = 0x7fffffff;
            if (lane < NCTA) {
                float4 tc = __ldcg(&g_tri[lane]);
                cv = tc.x; cs = tc.y; ci = __float_as_int(tc.z);
            }
            float mv = cv; int mi = ci;
#pragma unroll
            for (int o = 16; o; o >>= 1) {
                float ov = __shfl_xor_sync(0xffffffffu, mv, o);
                int   oi = __shfl_xor_sync(0xffffffffu, mi, o);
                if (ov > mv || (ov == mv && oi < mi)) { mv = ov; mi = oi; }
            }
            float gmax = mv;
            float term = (lane < NCTA && cv != -INFINITY) ? cs * expf(cv - gmax) : 0.f;
            float gsum = wsum(term);
            if (lane == 0) {
                int cur    = sh_nused;
                int isnew  = (mi == NPCC) ? 1 : 0;
                int chosen = isnew ? cur : mi;
                g_colors[v] = chosen;
                sh_nused = cur + isnew;
                // max(probs) = 1/gsum ; lpp += log(maxp+1e-8) - log(1e-8)
                lpp += logf(1.f / gsum + 1e-8f) + 18.420680743952367f;
            }
        }
        __syncthreads();   // publish sh_nused + colors[v] before next Stage A
    }

    // ---------------- output: [colors..., loss] ----------------
    for (int i = gtid; i < NV && i < out_size; i += GSTRIDE)
        out[i] = (float)__ldcg(&g_colors[i]);
    if (rank == 0 && tid == 0 && out_size > NV) {
        float loss = ((float)sh_nused - (float)baseline[0]) * lpp / (float)NV + 0.05f * regv;
        out[NV] = loss;
    }
}

extern "C" void kernel_launch(void* const* d_in, const int* in_sizes, int n_in,
                              void* d_out, int out_size) {
    (void)in_sizes; (void)n_in;
    gc_kernel<<<NCTA, TPB>>>(
        (const int*)d_in[0],    // adj      (8192,16)
        (const float*)d_in[1],  // W        (768,512)
        (const float*)d_in[2],  // a        (1024,)
        (const float*)d_in[3],  // fc1_w    (512,512)
        (const float*)d_in[4],  // fc1_b
        (const float*)d_in[5],  // fc2_w    (400,512)
        (const float*)d_in[6],  // fc2_b
        (const float*)d_in[7],  // fc3_w    (257,400)
        (const float*)d_in[8],  // fc3_b
        (const int*)d_in[9],    // baseline
        (float*)d_out, out_size);
}

// round 4
// speedup vs baseline: 2.0856x; 1.2343x over previous
#include <cuda_runtime.h>
#include <math.h>

#define NV    8192
#define DEG   16
#define EMBD  512
#define NPCC  256
#define NL    257
#define H2D   400
#define TPB   512
#define JS2   416
#define JS3   304

// ---------------- persistent device scratch ----------------
__device__ __align__(16) float g_z[(size_t)NV * EMBD];     // z[u] = emb[u] @ W[:512]
__device__ __align__(16) float g_TI1[128 * 512 * 4];       // fc1^T interleaved
__device__ __align__(16) float g_TIz[128 * 512 * 4];       // W[:512] interleaved (for z cols)
__device__ __align__(16) float g_TI2[128 * JS2 * 4];       // fc2^T interleaved, j-padded
__device__ __align__(16) float g_TI3[128 * JS3 * 4];       // fc3^T interleaved, j+k padded
__device__ __align__(16) float g_h1[EMBD];
__device__ __align__(16) float g_h2[512];                  // padded to 512, tail zeroed
__device__ float4 g_tri[16];
__device__ float  g_red[16 * 4];

#define SMEM_BYTES 72448

__device__ __forceinline__ float wsum(float v) {
#pragma unroll
    for (int o = 16; o; o >>= 1) v += __shfl_xor_sync(0xffffffffu, v, o);
    return v;
}
__device__ __forceinline__ float dot4(float4 a, float4 b) {
    return a.x * b.x + a.y * b.y + a.z * b.z + a.w * b.w;
}

#define CLUSTER_SYNC() do { \
    asm volatile("barrier.cluster.arrive.aligned;" ::: "memory"); \
    asm volatile("barrier.cluster.wait.aligned;"   ::: "memory"); } while (0)

// column-GEMV inner loop: N4 float4 steps; weights at stride js float4s
template<int N4, bool GIN>
__device__ __forceinline__ float colgemv(const float4* __restrict__ w4, int js,
                                         const float4* __restrict__ in4) {
    float ax = 0.f, ay = 0.f, az = 0.f, aw = 0.f;
#pragma unroll
    for (int i = 0; i < N4; i++) {
        float4 w = w4[(size_t)i * js];
        float4 x = GIN ? __ldcg(in4 + i) : in4[i];
        ax = fmaf(w.x, x.x, ax); ay = fmaf(w.y, x.y, ay);
        az = fmaf(w.z, x.z, az); aw = fmaf(w.w, x.w, aw);
    }
    return (ax + ay) + (az + aw);
}

template<int C>
__device__ __forceinline__ void gc_body(
    const int* __restrict__ adj, const float* __restrict__ W,
    const float* __restrict__ a, const float* __restrict__ fc1w,
    const float* __restrict__ fc1b, const float* __restrict__ fc2w,
    const float* __restrict__ fc2b, const float* __restrict__ fc3w,
    const float* __restrict__ fc3b, const int* __restrict__ baseline,
    float* __restrict__ out, int out_size)
{
    extern __shared__ unsigned char dynsmem[];
    float* sh_h    = (float*)dynsmem;            // 16*512
    float* sh_ne   = sh_h + 16 * EMBD;           // 512
    float* sh_part = sh_ne + EMBD;               // 512
    float* sh_a2   = sh_part + EMBD;             // 512
    float* sh_e    = sh_a2 + EMBD;               // 16
    float* sh_loc  = sh_e + 16;                  // 64
    float* sh_red  = sh_loc + 64;                // 16
    int*   sh_colors = (int*)(sh_red + 16);      // 8192
    int*   sh_nbrc   = sh_colors + NV;           // 16
    int*   sh_misc   = sh_nbrc + 16;             // [0]=nused

    const int rank = blockIdx.x;
    const int tid  = threadIdx.x;
    const int warp = tid >> 5, lane = tid & 31;
    const int gtid = rank * TPB + tid;
    const int GS   = C * TPB;

    float lpp = 0.f, regv = 0.f;

    // ---------------- per-launch init ----------------
    {
        float4 z4 = make_float4(0.f, 0.f, 0.f, 0.f);
        float4* zp = (float4*)g_z;
        const size_t nz4 = (size_t)NV * EMBD / 4;
        for (size_t i = gtid; i < nz4; i += GS) zp[i] = z4;
    }
    for (int d = gtid; d < 128 * 512 * 4; d += GS) {
        int c4 = d & 3, j = (d >> 2) & 511, k = (d >> 11) * 4 + c4;
        g_TI1[d] = fc1w[j * 512 + k];
        g_TIz[d] = W[k * 512 + j];
    }
    for (int d = gtid; d < 128 * JS2 * 4; d += GS) {
        int c4 = d & 3, j = (d >> 2) % JS2, k = (d / (JS2 * 4)) * 4 + c4;
        g_TI2[d] = (j < H2D) ? fc2w[j * 512 + k] : 0.f;
    }
    for (int d = gtid; d < 128 * JS3 * 4; d += GS) {
        int c4 = d & 3, j = (d >> 2) % JS3, k = (d / (JS3 * 4)) * 4 + c4;
        g_TI3[d] = (j < NL && k < H2D) ? fc3w[j * H2D + k] : 0.f;
    }
    if (gtid < 112) g_h2[400 + gtid] = 0.f;
    for (int i = tid; i < NV; i += TPB) sh_colors[i] = (i == 0) ? 0 : -1;
    for (int i = tid; i < EMBD; i += TPB) sh_a2[i] = a[EMBD + i];
    if (tid < 64) sh_loc[tid] = -INFINITY;
    if (tid == 0) sh_misc[0] = 1;

    // ---------------- Frobenius norms ----------------
    {
        float s[4] = {0.f, 0.f, 0.f, 0.f};
        for (int i = gtid; i < 768 * 512; i += GS) { float x = W[i];    s[0] += x * x; }
        for (int i = gtid; i < 512 * 512; i += GS) { float x = fc1w[i]; s[1] += x * x; }
        for (int i = gtid; i < 400 * 512; i += GS) { float x = fc2w[i]; s[2] += x * x; }
        for (int i = gtid; i < 257 * 400; i += GS) { float x = fc3w[i]; s[3] += x * x; }
#pragma unroll
        for (int m = 0; m < 4; m++) {
            float w = wsum(s[m]);
            __syncthreads();
            if (lane == 0) sh_red[warp] = w;
            __syncthreads();
            if (warp == 0) {
                float v2 = (lane < 16) ? sh_red[lane] : 0.f;
                v2 = wsum(v2);
                if (lane == 0) g_red[rank * 4 + m] = v2;
            }
            __syncthreads();
        }
    }
    CLUSTER_SYNC();   // init + norms visible cluster-wide

    if (rank == 0 && tid == 0) {
        for (int m = 0; m < 4; m++) {
            float ssq = 0.f;
            for (int c = 0; c < C; c++) ssq += __ldcg(&g_red[c * 4 + m]);
            regv += sqrtf(ssq);
        }
    }

    // geometry
    constexpr int O1  = 512 / C,  K1q = 128 / C;                 // P1: parts=C
    constexpr int O2  = 1024 / C, OfS = 512 / C, Ofr = H2D / C;  // P2: parts=C/2
    constexpr int K2q = 256 / C,  P2n = C / 2;
    constexpr int O3s = 512 / C,  O3r = (C == 16) ? 17 : 33;     // P3: parts=C
    constexpr int K3q = 128 / C;

    // ======================= sequential scan =======================
    for (int v = 1; v < NV; ++v) {
        // ---- Stage A: 16 neighbor rows, one per warp (h[0] == 0 identically) ----
        {
            int u = adj[v * DEG + warp];
            int c = sh_colors[u];
            if (lane == 0) sh_nbrc[warp] = c;
            const float4* z4 = (const float4*)(g_z + (size_t)u * EMBD);
            const float4* w4 = (c >= 0) ? (const float4*)(W + (size_t)(EMBD + c) * EMBD)
                                        : (const float4*)0;
            float4* hrow = (float4*)(sh_h + warp * EMBD);
            float d2 = 0.f;
#pragma unroll
            for (int i = 0; i < 4; i++) {
                int idx = lane + 32 * i;
                float4 hv = __ldcg(z4 + idx);
                if (w4) { float4 wv = w4[idx]; hv.x += wv.x; hv.y += wv.y; hv.z += wv.z; hv.w += wv.w; }
                hrow[idx] = hv;
                d2 += dot4(hv, ((const float4*)sh_a2)[idx]);
            }
            d2 = wsum(d2);
            if (lane == 0) sh_e[warp] = d2;
        }
        __syncthreads();

        // ---- softmax replicated per warp; new_e = elu(attn @ h) ----
        {
            float ev;
            if (lane == 0) ev = 0.f;                       // e_0 (self) = leaky(0) = 0
            else if (lane < 17) { float t = sh_e[lane - 1]; ev = (t > 0.f) ? t : 0.2f * t; }
            else ev = -INFINITY;
            float m = ev;
#pragma unroll
            for (int o = 16; o; o >>= 1) m = fmaxf(m, __shfl_xor_sync(0xffffffffu, m, o));
            float p = (lane < 17) ? expf(ev - m) : 0.f;
            float s = wsum(p);
            float attn = p / s;

            int j = tid;
            float acc = 0.f;
#pragma unroll
            for (int t = 1; t < 17; t++)
                acc += __shfl_sync(0xffffffffu, attn, t) * sh_h[(t - 1) * EMBD + j];
            sh_ne[j] = (acc > 0.f) ? acc : expm1f(acc);
        }
        __syncthreads();

        // ---- P1: h1 = lrelu(fc1 @ ne + b1), column-parallel ----
        {
            int p = tid / O1, jloc = tid % O1;
            int j = rank * O1 + jloc;
            const float4* w4  = (const float4*)g_TI1 + (size_t)(p * K1q) * 512 + j;
            const float4* in4 = (const float4*)sh_ne + p * K1q;
            sh_part[tid] = colgemv<K1q, false>(w4, 512, in4);
            __syncthreads();
            if (tid < O1) {
                float sum = 0.f;
#pragma unroll
                for (int q = 0; q < C; q++) sum += sh_part[q * O1 + tid];
                int jj = rank * O1 + tid;
                float h = sum + fc1b[jj];
                __stcg(&g_h1[jj], (h > 0.f) ? h : 0.01f * h);
            }
        }
        CLUSTER_SYNC();   // sync1: h1 visible

        // ---- P2: h2 (fc2 @ h1) + z[v] (ne @ W[:512]), merged column-parallel ----
        {
            int p = tid / O2, jloc = tid % O2;
            float acc;
            if (jloc < OfS) {
                int j = rank * Ofr + jloc;   // padded; dummy cols read zero weights
                const float4* w4  = (const float4*)g_TI2 + (size_t)(p * K2q) * JS2 + j;
                const float4* in4 = (const float4*)g_h1 + p * K2q;
                acc = colgemv<K2q, true>(w4, JS2, in4);
            } else {
                int jz = rank * OfS + (jloc - OfS);
                const float4* w4  = (const float4*)g_TIz + (size_t)(p * K2q) * 512 + jz;
                const float4* in4 = (const float4*)sh_ne + p * K2q;
                acc = colgemv<K2q, false>(w4, 512, in4);
            }
            sh_part[tid] = acc;
            __syncthreads();
            if (tid < O2) {
                float sum = 0.f;
#pragma unroll
                for (int q = 0; q < P2n; q++) sum += sh_part[q * O2 + tid];
                if (tid < OfS) {
                    if (tid < Ofr) {
                        int j = rank * Ofr + tid;
                        float h = sum + fc2b[j];
                        __stcg(&g_h2[j], (h > 0.f) ? h : 0.01f * h);
                    }
                } else {
                    int jz = rank * OfS + (tid - OfS);
                    __stcg(&g_z[(size_t)v * EMBD + jz], sum);
                }
            }
        }
        CLUSTER_SYNC();   // sync2: h2 + z visible

        // ---- P3: logits slice + mask + local (max,sum,argmax) ----
        {
            int p = tid / O3s, jloc = tid % O3s;
            int j = rank * O3r + jloc;   // padded j / k: zero weights
            const float4* w4  = (const float4*)g_TI3 + (size_t)(p * K3q) * JS3 + j;
            const float4* in4 = (const float4*)g_h2 + p * K3q;
            sh_part[tid] = colgemv<K3q, true>(w4, JS3, in4);
            __syncthreads();
            if (tid < O3s) {
                float sum = 0.f;
#pragma unroll
                for (int q = 0; q < C; q++) sum += sh_part[q * O3s + tid];
                int j2 = rank * O3r + tid;
                float mlv = -INFINITY;
                if (tid < O3r && j2 < NL) {
                    float L = sum + fc3b[j2];
                    int nused = sh_misc[0];
                    bool irrel = (j2 >= nused) && (j2 < NPCC);
                    bool am = false;
#pragma unroll
                    for (int t = 0; t < 16; t++) am |= (sh_nbrc[t] == j2);
                    mlv = (irrel || am) ? -INFINITY : L;
                }
                sh_loc[tid] = mlv;
            }
            __syncthreads();
            if (warp == 0) {
                float v1 = sh_loc[lane];      int i1 = lane;
                float v2 = sh_loc[lane + 32]; int i2 = lane + 32;
                if (v2 > v1) { v1 = v2; i1 = i2; }
                float rv = v1; int ri = i1;
#pragma unroll
                for (int o = 16; o; o >>= 1) {
                    float ov = __shfl_xor_sync(0xffffffffu, rv, o);
                    int   oi = __shfl_xor_sync(0xffffffffu, ri, o);
                    if (ov > rv || (ov == rv && oi < ri)) { rv = ov; ri = oi; }
                }
                float lmax = rv;
                float t0 = (sh_loc[lane]      == -INFINITY) ? 0.f : expf(sh_loc[lane]      - lmax);
                float t1 = (sh_loc[lane + 32] == -INFINITY) ? 0.f : expf(sh_loc[lane + 32] - lmax);
                float lsum = wsum(t0 + t1);
                if (lmax == -INFINITY) lsum = 0.f;
                if (lane == 0)
                    g_tri[rank] = make_float4(lmax, lsum, __int_as_float(rank * O3r + ri), 0.f);
            }
        }
        CLUSTER_SYNC();   // sync3: triples visible

        // ---- E: combine (replicated), commit color/nused/lpp ----
        if (warp == 0) {
            float cv = -INFINITY, cs = 0.f; int ci = 0x7fffffff;
            if (lane < C) {
                float4 t4 = __ldcg(&g_tri[lane]);
                cv = t4.x; cs = t4.y; ci = __float_as_int(t4.z);
            }
            float mv = cv; int mi = ci;
#pragma unroll
            for (int o = 16; o; o >>= 1) {
                float ov = __shfl_xor_sync(0xffffffffu, mv, o);
                int   oi = __shfl_xor_sync(0xffffffffu, mi, o);
                if (ov > mv || (ov == mv && oi < mi)) { mv = ov; mi = oi; }
            }
            float term = (lane < C && cv != -INFINITY) ? cs * expf(cv - mv) : 0.f;
            float gsum = wsum(term);
            if (lane == 0) {
                int cur    = sh_misc[0];
                int isnew  = (mi == NPCC) ? 1 : 0;
                sh_colors[v] = isnew ? cur : mi;
                sh_misc[0] = cur + isnew;
                lpp += logf(1.f / gsum + 1e-8f) + 18.420680743952367f;
            }
        }
        __syncthreads();
    }

    // ---------------- output: [colors..., loss] ----------------
    for (int i = gtid; i < NV && i < out_size; i += GS)
        out[i] = (float)sh_colors[i];
    if (rank == 0 && tid == 0 && out_size > NV) {
        float loss = ((float)sh_misc[0] - (float)baseline[0]) * lpp / (float)NV + 0.05f * regv;
        out[NV] = loss;
    }
}

#define PARAMS const int* adj, const float* W, const float* a, const float* fc1w, \
               const float* fc1b, const float* fc2w, const float* fc2b,           \
               const float* fc3w, const float* fc3b, const int* baseline,         \
               float* out, int out_size
#define ARGS adj, W, a, fc1w, fc1b, fc2w, fc2b, fc3w, fc3b, baseline, out, out_size

__global__ void __launch_bounds__(TPB, 1)
gc_k16(PARAMS) { gc_body<16>(ARGS); }

__global__ void __launch_bounds__(TPB, 1) __cluster_dims__(8, 1, 1)
gc_k8(PARAMS) { gc_body<8>(ARGS); }

extern "C" void kernel_launch(void* const* d_in, const int* in_sizes, int n_in,
                              void* d_out, int out_size) {
    (void)in_sizes; (void)n_in;
    const int*   adj  = (const int*)d_in[0];
    const float* W    = (const float*)d_in[1];
    const float* a    = (const float*)d_in[2];
    const float* fc1w = (const float*)d_in[3];
    const float* fc1b = (const float*)d_in[4];
    const float* fc2w = (const float*)d_in[5];
    const float* fc2b = (const float*)d_in[6];
    const float* fc3w = (const float*)d_in[7];
    const float* fc3b = (const float*)d_in[8];
    const int*   bl   = (const int*)d_in[9];
    float* out = (float*)d_out;

    cudaFuncSetAttribute(gc_k16, cudaFuncAttributeNonPortableClusterSizeAllowed, 1);
    cudaFuncSetAttribute(gc_k16, cudaFuncAttributeMaxDynamicSharedMemorySize, SMEM_BYTES);
    cudaFuncSetAttribute(gc_k8,  cudaFuncAttributeMaxDynamicSharedMemorySize, SMEM_BYTES);
    (void)cudaGetLastError();

    int maxC = 0;
    cudaLaunchConfig_t q = {};
    q.gridDim = {16, 1, 1}; q.blockDim = {TPB, 1, 1};
    q.dynamicSmemBytes = SMEM_BYTES; q.stream = 0;
    cudaError_t qe = cudaOccupancyMaxPotentialClusterSize(&maxC, gc_k16, &q);
    (void)cudaGetLastError();

    if (qe == cudaSuccess && maxC >= 16) {
        cudaLaunchConfig_t cfg = {};
        cfg.gridDim = {16, 1, 1}; cfg.blockDim = {TPB, 1, 1};
        cfg.dynamicSmemBytes = SMEM_BYTES; cfg.stream = 0;
        cudaLaunchAttribute at[1];
        at[0].id = cudaLaunchAttributeClusterDimension;
        at[0].val.clusterDim = {16, 1, 1};
        cfg.attrs = at; cfg.numAttrs = 1;
        cudaLaunchKernelEx(&cfg, gc_k16, adj, W, a, fc1w, fc1b, fc2w, fc2b,
                           fc3w, fc3b, bl, out, out_size);
    } else {
        gc_k8<<<8, TPB, SMEM_BYTES>>>(adj, W, a, fc1w, fc1b, fc2w, fc2b,
                                      fc3w, fc3b, bl, out, out_size);
    }
}